// round 6
// baseline (speedup 1.0000x reference)
#include <cuda_runtime.h>
#include <cstdint>

// Problem constants (fixed shapes per reference)
#define NSPANS 4096
#define TMAX   16
#define HDIM   768
#define H4     192          // HDIM / 4 (float4 lanes per row)
#define NPAIRS 16384
#define SL     2048         // S * L
#define PPB    8            // pairs per block in kernel 2

// Scratch: only the mean vectors [NSPANS, HDIM] = 12.6 MB.
// first/last are verbatim hidden rows -> re-gathered from L2 in kernel 2.
__device__ float4 g_mean[NSPANS * H4];
// Per-span {first_row_off, last_row_off} in float4 units into hidden.
__device__ int2 g_info[NSPANS];

// Kernel 1: 2 spans per block (384 threads: lanes 0-191 span A, 192-383 span B).
// Fixed fully-unrolled TMAX loop with clamped token index -> 16 independent
// loads in flight per thread (clamped duplicates are L1 hits, weight 0).
__global__ __launch_bounds__(384) void reprs_kernel(
    const float* __restrict__ hidden,
    const int*   __restrict__ span_doc,
    const int*   __restrict__ span_tok,
    const int*   __restrict__ span_len)
{
    const int tid  = threadIdx.x;
    const int half = tid / H4;                // 0 or 1
    const int lane = tid - half * H4;         // 0..191
    const int n    = blockIdx.x * 2 + half;

    __shared__ int s_tok[2][TMAX];
    if (lane < TMAX)
        s_tok[half][lane] = __ldg(span_tok + n * TMAX + lane);
    __syncthreads();

    const int doc   = __ldg(span_doc + n);
    const int len   = __ldg(span_len + n);    // 1..16
    const int lenm1 = len - 1;

    const float4* __restrict__ base =
        reinterpret_cast<const float4*>(hidden) + (size_t)doc * SL * H4;

    float4 acc = make_float4(0.f, 0.f, 0.f, 0.f);

    #pragma unroll
    for (int t = 0; t < TMAX; ++t) {
        const int tt = (t < len) ? t : lenm1;     // clamp -> L1-hit duplicate
        const float w = (t < len) ? 1.0f : 0.0f;
        const float4 v = __ldg(base + (size_t)s_tok[half][tt] * H4 + lane);
        acc.x += v.x * w; acc.y += v.y * w;
        acc.z += v.z * w; acc.w += v.w * w;
    }

    const float inv = 1.0f / (float)len;
    g_mean[n * H4 + lane] = make_float4(acc.x * inv, acc.y * inv,
                                        acc.z * inv, acc.w * inv);

    if (lane == 0) {
        const int docbase = doc * SL;
        g_info[n] = make_int2((docbase + s_tok[half][0]) * H4,
                              (docbase + s_tok[half][lenm1]) * H4);
    }
}

// Kernel 2: 8 pairs per block. Threads 0..7 resolve all pair indices into
// shared once (kills the pair->info->data pointer chase per pair), then the
// unrolled loop streams the eight 4608-float rows with evict-first stores.
// Output row layout (float4 units):
//   [ first_i(192) mean_i(192) last_i(192) first_j(192) mean_j(192) last_j(192) ]
// Thread tid covers lanes {tid, tid+384, tid+768}:
//   tid     : tid<192 -> first_i  else mean_i
//   tid+384 : tid<192 -> last_i   else first_j
//   tid+768 : tid<192 -> mean_j   else last_j
__global__ __launch_bounds__(384) void pairs_kernel(
    const float* __restrict__ hidden,
    const int*   __restrict__ pair_i,
    const int*   __restrict__ pair_j,
    float4*      __restrict__ out)
{
    const int tid   = threadIdx.x;
    const int pbase = blockIdx.x * PPB;

    // per pair: {ii.x, ii.y, pi*H4} and {ij.x, ij.y, pj*H4}
    __shared__ int s_a[PPB][3];
    __shared__ int s_b[PPB][3];

    if (tid < PPB) {
        const int p  = pbase + tid;
        const int pi = __ldg(pair_i + p);
        const int pj = __ldg(pair_j + p);
        const int2 ii = __ldg(&g_info[pi]);
        const int2 ij = __ldg(&g_info[pj]);
        s_a[tid][0] = ii.x; s_a[tid][1] = ii.y; s_a[tid][2] = pi * H4;
        s_b[tid][0] = ij.x; s_b[tid][1] = ij.y; s_b[tid][2] = pj * H4;
    }
    __syncthreads();

    const float4* __restrict__ hid4 = reinterpret_cast<const float4*>(hidden);
    const bool lo = (tid < 192);
    const int  t2 = tid - 192;

    #pragma unroll 2
    for (int k = 0; k < PPB; ++k) {
        const int afirst = s_a[k][0], alast = s_a[k][1], amean = s_a[k][2];
        const int bfirst = s_b[k][0], blast = s_b[k][1], bmean = s_b[k][2];
        float4* __restrict__ o = out + (size_t)(pbase + k) * 1152;

        const float4 v0 = lo ? __ldg(hid4 + afirst + tid)
                             : __ldg(g_mean + amean + t2);
        const float4 v1 = lo ? __ldg(hid4 + alast + tid)
                             : __ldg(hid4 + bfirst + t2);
        const float4 v2 = lo ? __ldg(g_mean + bmean + tid)
                             : __ldg(hid4 + blast + t2);

        __stcs(o + tid,       v0);
        __stcs(o + tid + 384, v1);
        __stcs(o + tid + 768, v2);
    }
}

extern "C" void kernel_launch(void* const* d_in, const int* in_sizes, int n_in,
                              void* d_out, int out_size)
{
    const float* hidden   = (const float*)d_in[0];
    const int*   span_doc = (const int*)  d_in[1];
    const int*   span_tok = (const int*)  d_in[2];
    const int*   span_len = (const int*)  d_in[3];
    const int*   pair_i   = (const int*)  d_in[4];
    const int*   pair_j   = (const int*)  d_in[5];
    float4*      out      = (float4*)     d_out;

    reprs_kernel<<<NSPANS / 2, 384>>>(hidden, span_doc, span_tok, span_len);
    pairs_kernel<<<NPAIRS / PPB, 384>>>(hidden, pair_i, pair_j, out);
}

// round 7
// speedup vs baseline: 1.0215x; 1.0215x over previous
#include <cuda_runtime.h>
#include <cstdint>

// Problem constants (fixed shapes per reference)
#define NSPANS 4096
#define TMAX   16
#define HDIM   768
#define H4     192          // HDIM / 4 (float4 lanes per row)
#define NPAIRS 16384
#define SL     2048         // S * L

// Scratch: only the mean vectors [NSPANS, HDIM] = 12.6 MB.
// first/last are verbatim hidden rows -> re-gathered from L2 in kernel 2.
__device__ float4 g_mean[NSPANS * H4];
// Per-span {first_row_off, last_row_off} in float4 units into hidden.
__device__ int2 g_info[NSPANS];

// Kernel 1: 2 spans per block (384 threads: lanes 0-191 span A, 192-383 span B).
// Fixed fully-unrolled TMAX loop with clamped token index -> 16 independent
// loads in flight per thread (clamped duplicates are L1 hits, weight 0).
__global__ __launch_bounds__(384) void reprs_kernel(
    const float* __restrict__ hidden,
    const int*   __restrict__ span_doc,
    const int*   __restrict__ span_tok,
    const int*   __restrict__ span_len)
{
    const int tid  = threadIdx.x;
    const int half = tid / H4;                // 0 or 1
    const int lane = tid - half * H4;         // 0..191
    const int n    = blockIdx.x * 2 + half;

    __shared__ int s_tok[2][TMAX];
    if (lane < TMAX)
        s_tok[half][lane] = __ldg(span_tok + n * TMAX + lane);
    __syncthreads();

    const int doc   = __ldg(span_doc + n);
    const int len   = __ldg(span_len + n);    // 1..16
    const int lenm1 = len - 1;

    const float4* __restrict__ base =
        reinterpret_cast<const float4*>(hidden) + (size_t)doc * SL * H4;

    float4 acc = make_float4(0.f, 0.f, 0.f, 0.f);

    #pragma unroll
    for (int t = 0; t < TMAX; ++t) {
        const int tt = (t < len) ? t : lenm1;     // clamp -> L1-hit duplicate
        const float w = (t < len) ? 1.0f : 0.0f;
        const float4 v = __ldg(base + (size_t)s_tok[half][tt] * H4 + lane);
        acc.x += v.x * w; acc.y += v.y * w;
        acc.z += v.z * w; acc.w += v.w * w;
    }

    const float inv = 1.0f / (float)len;
    g_mean[n * H4 + lane] = make_float4(acc.x * inv, acc.y * inv,
                                        acc.z * inv, acc.w * inv);

    if (lane == 0) {
        const int docbase = doc * SL;
        g_info[n] = make_int2((docbase + s_tok[half][0]) * H4,
                              (docbase + s_tok[half][lenm1]) * H4);
    }
}

// Kernel 2 (R5 shape — best measured): one block per pair, 384 threads.
// Output row layout (float4 units):
//   [ first_i(192) mean_i(192) last_i(192) first_j(192) mean_j(192) last_j(192) ]
// Thread tid covers lanes {tid, tid+384, tid+768}:
//   tid     : tid<192 -> first_i  else mean_i
//   tid+384 : tid<192 -> last_i   else first_j
//   tid+768 : tid<192 -> mean_j   else last_j
// first/last come straight from L2-resident hidden; mean from g_mean.
// All three loads issued before the evict-first stores.
__global__ __launch_bounds__(384) void pairs_kernel(
    const float* __restrict__ hidden,
    const int*   __restrict__ pair_i,
    const int*   __restrict__ pair_j,
    float4*      __restrict__ out)
{
    const int p   = blockIdx.x;
    const int tid = threadIdx.x;
    const int pi  = __ldg(pair_i + p);
    const int pj  = __ldg(pair_j + p);

    const int2 ii = __ldg(&g_info[pi]);
    const int2 ij = __ldg(&g_info[pj]);

    const float4* __restrict__ hid4 = reinterpret_cast<const float4*>(hidden);
    float4* __restrict__ o = out + (size_t)p * 1152;

    const bool lo = (tid < 192);
    const int  t2 = tid - 192;

    const float4 v0 = lo ? __ldg(hid4 + ii.x + tid)
                         : __ldg(g_mean + pi * H4 + t2);
    const float4 v1 = lo ? __ldg(hid4 + ii.y + tid)
                         : __ldg(hid4 + ij.x + t2);
    const float4 v2 = lo ? __ldg(g_mean + pj * H4 + tid)
                         : __ldg(hid4 + ij.y + t2);

    __stcs(o + tid,       v0);
    __stcs(o + tid + 384, v1);
    __stcs(o + tid + 768, v2);
}

extern "C" void kernel_launch(void* const* d_in, const int* in_sizes, int n_in,
                              void* d_out, int out_size)
{
    const float* hidden   = (const float*)d_in[0];
    const int*   span_doc = (const int*)  d_in[1];
    const int*   span_tok = (const int*)  d_in[2];
    const int*   span_len = (const int*)  d_in[3];
    const int*   pair_i   = (const int*)  d_in[4];
    const int*   pair_j   = (const int*)  d_in[5];
    float4*      out      = (float4*)     d_out;

    reprs_kernel<<<NSPANS / 2, 384>>>(hidden, span_doc, span_tok, span_len);
    pairs_kernel<<<NPAIRS, 384>>>(hidden, pair_i, pair_j, out);
}